// round 4
// baseline (speedup 1.0000x reference)
#include <cuda_runtime.h>
#include <math.h>

#define NN   250000
#define EE   1000000
#define BB   25
#define NX_  8
#define NY_  9
#define NCC  72
#define MM   1800
#define GRD  16
#define NOUTC 2
#define EPSB 1e-5f

// ---------------- scratch (device globals; no allocation allowed) -------------
__device__ float d_z[(size_t)NN * 8 * 32];   // per-node spline projections (max 256MB)
__device__ float d_xB[NN * 32];              // conv outputs (pre-BN, mean-aggregated)
__device__ int   d_deg[NN];
__device__ int   d_off[NN + 1];              // CSR offsets
__device__ int   d_cur[NN];                  // fill cursors
__device__ int   d_part[1024];               // scan partials
__device__ int   d_pbase[1024];
__device__ int   d_esrc[EE];                 // CSR-ordered source node ids
__device__ __align__(16) float d_sbas[(size_t)EE * 8];  // CSR-ordered basis (32MB)
__device__ int   d_clu[NN];
__device__ float d_stats[64];                // [sum(C), sumsq(C)]
__device__ __align__(16) float d_bnsc[32];   // BN scale per channel
__device__ __align__(16) float d_bnsh[32];   // BN shift per channel
__device__ float d_xp[MM * 32];              // pooled features (max pooled)
__device__ float d_pp[MM * 3];               // pooled positions
__device__ int   d_cnt[MM];
__device__ unsigned char d_adj[MM * MM];
__device__ int   d_maxv;                     // float bits (non-negative)
__device__ int   d_nm;                       // number of non-empty cells
__device__ float d_pz[MM * 8 * 32];          // pooled per-node projections
__device__ float d_xt[MM * 32];              // pooled conv raw output
__device__ float d_xu[MM * 32];              // pooled conv post-BN output
__device__ float d_xg[BB * GRD * 32];        // MaxPoolingX output

// ---------------- helpers ----------------------------------------------------
__device__ __forceinline__ void basis8(float p0, float p1, float p2, float* b) {
    p0 = fminf(fmaxf(p0, 0.f), 1.f);
    p1 = fminf(fmaxf(p1, 0.f), 1.f);
    p2 = fminf(fmaxf(p2, 0.f), 1.f);
    float q0 = 1.f - p0, q1 = 1.f - p1, q2 = 1.f - p2;
    b[0] = q0 * q1 * q2; b[1] = p0 * q1 * q2;
    b[2] = q0 * p1 * q2; b[3] = p0 * p1 * q2;
    b[4] = q0 * q1 * p2; b[5] = p0 * q1 * p2;
    b[6] = q0 * p1 * p2; b[7] = p0 * p1 * p2;
}

__device__ __forceinline__ void atomicMaxFloatPos(float* addr, float v) {
    atomicMax(reinterpret_cast<int*>(addr), __float_as_int(v));
}

// ---------------- degree + CSR build -----------------------------------------
__global__ void k_deg(const int* __restrict__ dst) {
    int e = blockIdx.x * blockDim.x + threadIdx.x;
    if (e < EE) atomicAdd(&d_deg[dst[e]], 1);
}

__global__ void k_scanA() {  // 256 threads/block, 977 blocks
    __shared__ int sm[256];
    int i = blockIdx.x * 256 + threadIdx.x;
    int v = (i < NN) ? d_deg[i] : 0;
    sm[threadIdx.x] = v;
    __syncthreads();
    for (int off = 1; off < 256; off <<= 1) {
        int t = (threadIdx.x >= off) ? sm[threadIdx.x - off] : 0;
        __syncthreads();
        sm[threadIdx.x] += t;
        __syncthreads();
    }
    if (i < NN) d_off[i] = sm[threadIdx.x] - v;  // exclusive within block
    if (threadIdx.x == 255) d_part[blockIdx.x] = sm[255];
}

__global__ void k_scanB(int nparts) {  // 1 block, 1024 threads
    __shared__ int sm[1024];
    int v = (threadIdx.x < nparts) ? d_part[threadIdx.x] : 0;
    sm[threadIdx.x] = v;
    __syncthreads();
    for (int off = 1; off < 1024; off <<= 1) {
        int t = (threadIdx.x >= off) ? sm[threadIdx.x - off] : 0;
        __syncthreads();
        sm[threadIdx.x] += t;
        __syncthreads();
    }
    if (threadIdx.x < nparts) d_pbase[threadIdx.x] = sm[threadIdx.x] - v;
}

__global__ void k_scanC() {
    int i = blockIdx.x * blockDim.x + threadIdx.x;
    if (i < NN) d_off[i] += d_pbase[i >> 8];
    if (i == 0) d_off[NN] = EE;
}

__global__ void k_fill(const int* __restrict__ src, const int* __restrict__ dst,
                       const float* __restrict__ ea) {
    int e = blockIdx.x * blockDim.x + threadIdx.x;
    if (e >= EE) return;
    int d = dst[e];
    int slot = d_off[d] + atomicAdd(&d_cur[d], 1);
    d_esrc[slot] = src[e];
    float bs[8];
    basis8(ea[3 * e + 0], ea[3 * e + 1], ea[3 * e + 2], bs);
    float4* p = reinterpret_cast<float4*>(d_sbas + (size_t)slot * 8);
    p[0] = make_float4(bs[0], bs[1], bs[2], bs[3]);
    p[1] = make_float4(bs[4], bs[5], bs[6], bs[7]);
}

// ---------------- BN constants ------------------------------------------------
template <int C>
__global__ void k_mkbn(const float* __restrict__ g, const float* __restrict__ b,
                       float cnt) {
    int c = threadIdx.x;  // C threads
    float mean = d_stats[c] / cnt;
    float var = d_stats[C + c] / cnt - mean * mean;
    float s = rsqrtf(var + EPSB) * g[c];
    d_bnsc[c] = s;
    d_bnsh[c] = b[c] - mean * s;
}

// ---------------- node projection: z[n][c][s] = bnrelu(x[n]) . W[s][:,c] -------
template <int CIN, int COUT, bool BN>
__global__ void k_nproj(const float* __restrict__ xin, const float* __restrict__ W) {
    __shared__ float Wsh[CIN * COUT * 8];    // layout [(ci*COUT + c)*8 + s]
    __shared__ float sc[CIN], sh[CIN];
    for (int i = threadIdx.x; i < 8 * CIN * COUT; i += blockDim.x) {
        int c = i % COUT;
        int t = i / COUT;
        int ci = t % CIN;
        int s = t / CIN;
        Wsh[(ci * COUT + c) * 8 + s] = W[i];
    }
    if (BN && threadIdx.x < CIN) {
        sc[threadIdx.x] = d_bnsc[threadIdx.x];
        sh[threadIdx.x] = d_bnsh[threadIdx.x];
    }
    __syncthreads();
    int idx = blockIdx.x * blockDim.x + threadIdx.x;
    if (idx >= NN * COUT) return;
    int n = idx / COUT;
    int c = idx % COUT;
    float a0 = 0.f, a1 = 0.f, a2 = 0.f, a3 = 0.f, a4 = 0.f, a5 = 0.f, a6 = 0.f, a7 = 0.f;
#pragma unroll
    for (int ci = 0; ci < CIN; ci++) {
        float v = xin[(size_t)n * CIN + ci];
        if (BN) v = fmaxf(v * sc[ci] + sh[ci], 0.f);
        const float4* wp = reinterpret_cast<const float4*>(&Wsh[(ci * COUT + c) * 8]);
        float4 wa = wp[0], wb = wp[1];
        a0 += v * wa.x; a1 += v * wa.y; a2 += v * wa.z; a3 += v * wa.w;
        a4 += v * wb.x; a5 += v * wb.y; a6 += v * wb.z; a7 += v * wb.w;
    }
    float4* zp = reinterpret_cast<float4*>(d_z + ((size_t)n * COUT + c) * 8);
    zp[0] = make_float4(a0, a1, a2, a3);
    zp[1] = make_float4(a4, a5, a6, a7);
}

// ---------------- per-dst aggregation + mean + BN stats -----------------------
template <int COUT>
__global__ void k_aggr() {
    constexpr int SUB = 32 / COUT;
    int gwarp = (blockIdx.x * blockDim.x + threadIdx.x) >> 5;
    int lane = threadIdx.x & 31;
    int sub = lane / COUT;
    int c = lane % COUT;
    int nwarps = (gridDim.x * blockDim.x) >> 5;
    float ssum = 0.f, ssq = 0.f;
    for (int d0 = gwarp * SUB; d0 < NN; d0 += nwarps * SUB) {
        int d = d0 + sub;
        if (d < NN) {
            int st = d_off[d], en = d_off[d + 1];
            float acc = 0.f;
            for (int j = st; j < en; j++) {
                int s = d_esrc[j];
                const float4* zp = reinterpret_cast<const float4*>(
                    d_z + ((size_t)s * COUT + c) * 8);
                float4 za = zp[0], zb = zp[1];
                const float4* bp = reinterpret_cast<const float4*>(
                    d_sbas + (size_t)j * 8);
                float4 ba = bp[0], bb = bp[1];
                acc += ba.x * za.x + ba.y * za.y + ba.z * za.z + ba.w * za.w +
                       bb.x * zb.x + bb.y * zb.y + bb.z * zb.z + bb.w * zb.w;
            }
            float o = acc / fmaxf((float)(en - st), 1.f);
            d_xB[(size_t)d * COUT + c] = o;
            ssum += o;
            ssq += o * o;
        }
    }
    __shared__ float ss[32], s2[32];
    if (threadIdx.x < 32) { ss[threadIdx.x] = 0.f; s2[threadIdx.x] = 0.f; }
    __syncthreads();
    atomicAdd(&ss[c], ssum);
    atomicAdd(&s2[c], ssq);
    __syncthreads();
    if (threadIdx.x < COUT) {
        atomicAdd(&d_stats[threadIdx.x], ss[threadIdx.x]);
        atomicAdd(&d_stats[COUT + threadIdx.x], s2[threadIdx.x]);
    }
}

// ---------------- voxel pooling (BN5+relu fused on read) ----------------------
__global__ void k_cluster(const float* __restrict__ pos, const int* __restrict__ batch) {
    int n = blockIdx.x * blockDim.x + threadIdx.x;
    if (n >= NN) return;
    float p0 = pos[3 * n + 0], p1 = pos[3 * n + 1], p2 = pos[3 * n + 2];
    int cx = min(max((int)floorf(p0 / 16.0f), 0), NX_ - 1);
    int cy = min(max((int)floorf(p1 / 12.0f), 0), NY_ - 1);
    int cl = batch[n] * NCC + cy * NX_ + cx;
    d_clu[n] = cl;
    atomicAdd(&d_cnt[cl], 1);
    atomicAdd(&d_pp[cl * 3 + 0], p0);
    atomicAdd(&d_pp[cl * 3 + 1], p1);
    atomicAdd(&d_pp[cl * 3 + 2], p2);
    const float4* xr = reinterpret_cast<const float4*>(d_xB + (size_t)n * 32);
    const float4* scp = reinterpret_cast<const float4*>(d_bnsc);
    const float4* shp = reinterpret_cast<const float4*>(d_bnsh);
#pragma unroll
    for (int i = 0; i < 8; i++) {
        float4 v = xr[i];
        float4 s4 = scp[i], h4 = shp[i];
        atomicMaxFloatPos(&d_xp[cl * 32 + 4 * i + 0], fmaxf(v.x * s4.x + h4.x, 0.f));
        atomicMaxFloatPos(&d_xp[cl * 32 + 4 * i + 1], fmaxf(v.y * s4.y + h4.y, 0.f));
        atomicMaxFloatPos(&d_xp[cl * 32 + 4 * i + 2], fmaxf(v.z * s4.z + h4.z, 0.f));
        atomicMaxFloatPos(&d_xp[cl * 32 + 4 * i + 3], fmaxf(v.w * s4.w + h4.w, 0.f));
    }
}

__global__ void k_ppfin() {
    int m = blockIdx.x * blockDim.x + threadIdx.x;
    if (m >= MM) return;
    float c = fmaxf((float)d_cnt[m], 1.f);
    d_pp[m * 3 + 0] /= c;
    d_pp[m * 3 + 1] /= c;
    d_pp[m * 3 + 2] /= c;
    if (d_cnt[m] > 0) atomicAdd(&d_nm, 1);
}

__global__ void k_adj(const int* __restrict__ src, const int* __restrict__ dst) {
    int e = blockIdx.x * blockDim.x + threadIdx.x;
    if (e >= EE) return;
    int a = d_clu[src[e]], b = d_clu[dst[e]];
    if (a != b) d_adj[a * MM + b] = 1;
}

__global__ void k_maxv() {
    const int T = gridDim.x * blockDim.x;
    int t = blockIdx.x * blockDim.x + threadIdx.x;
    float mx = 0.f;
    for (int p = t; p < MM * MM; p += T) {
        if (d_adj[p]) {
            int r = p / MM, c = p % MM;
            mx = fmaxf(mx, fabsf(d_pp[c * 3 + 0] - d_pp[r * 3 + 0]));
            mx = fmaxf(mx, fabsf(d_pp[c * 3 + 1] - d_pp[r * 3 + 1]));
            mx = fmaxf(mx, fabsf(d_pp[c * 3 + 2] - d_pp[r * 3 + 2]));
        }
    }
    __shared__ float red[256];
    red[threadIdx.x] = mx;
    __syncthreads();
    for (int o = 128; o > 0; o >>= 1) {
        if (threadIdx.x < o) red[threadIdx.x] = fmaxf(red[threadIdx.x], red[threadIdx.x + o]);
        __syncthreads();
    }
    if (threadIdx.x == 0) atomicMax(&d_maxv, __float_as_int(red[0]));
}

// ---------------- pooled conv: per-node projections z = x . W[s] --------------
__global__ void k_pz(const float* __restrict__ xin, const float* __restrict__ W) {
    int t = blockIdx.x * blockDim.x + threadIdx.x;
    if (t >= MM * 8 * 32) return;
    int co = t & 31;
    int s = (t >> 5) & 7;
    int r = t >> 8;
    float acc = 0.f;
    const float* xr = &xin[r * 32];
    const float* wp = &W[s * 32 * 32 + co];
#pragma unroll
    for (int ci = 0; ci < 32; ci++) acc += xr[ci] * wp[ci * 32];
    d_pz[t] = acc;
}

// ---------------- pooled conv: per-dst aggregation ---------------------------
__global__ void k_pconv(float* __restrict__ out) {
    int c = blockIdx.x;
    int lane = threadIdx.x & 31;
    int w = threadIdx.x >> 5;  // 8 warps
    int g = c / NCC;
    int base = g * NCC;
    float inv = 0.5f / fmaxf(__int_as_float(d_maxv), 1e-9f);
    float pc0 = d_pp[c * 3 + 0], pc1 = d_pp[c * 3 + 1], pc2 = d_pp[c * 3 + 2];
    float acc = 0.f;
    int cnt = 0;
    for (int r = base + w; r < base + NCC; r += 8) {
        if (r == c || !d_adj[r * MM + c]) continue;
        cnt++;
        float bs[8];
        basis8((pc0 - d_pp[r * 3 + 0]) * inv + 0.5f,
               (pc1 - d_pp[r * 3 + 1]) * inv + 0.5f,
               (pc2 - d_pp[r * 3 + 2]) * inv + 0.5f, bs);
        const float* z = &d_pz[r * 256];
#pragma unroll
        for (int s = 0; s < 8; s++) acc += bs[s] * z[s * 32 + lane];
    }
    __shared__ float sa[8][32];
    __shared__ int scn[8];
    sa[w][lane] = acc;
    if (lane == 0) scn[w] = cnt;
    __syncthreads();
    if (w == 0) {
        float a = 0.f;
        int k = 0;
#pragma unroll
        for (int j = 0; j < 8; j++) { a += sa[j][lane]; k += scn[j]; }
        out[c * 32 + lane] = a / fmaxf((float)k, 1.f);
    }
}

// ---------------- pooled (masked) BN stats + finalize ------------------------
__global__ void k_pstats(const float* __restrict__ x) {
    int tid = threadIdx.x;  // one block, 1024 threads
    const int c = tid & 31;
    float sum = 0.f, sq = 0.f;
    for (int i = tid; i < MM * 32; i += 1024) {
        if (d_cnt[i >> 5] > 0) {
            float v = x[i];
            sum += v; sq += v * v;
        }
    }
    __shared__ float ss[32], s2[32];
    if (tid < 32) { ss[tid] = 0.f; s2[tid] = 0.f; }
    __syncthreads();
    atomicAdd(&ss[c], sum);
    atomicAdd(&s2[c], sq);
    __syncthreads();
    if (tid < 32) { d_stats[tid] = ss[tid]; d_stats[32 + tid] = s2[tid]; }
}

__global__ void k_pbn(const float* __restrict__ x, const float* __restrict__ g,
                      const float* __restrict__ b, float* __restrict__ out) {
    int i = blockIdx.x * blockDim.x + threadIdx.x;
    if (i >= MM * 32) return;
    int c = i & 31;
    float cntf = fmaxf((float)d_nm, 1.f);
    float mean = d_stats[c] / cntf;
    float var = d_stats[32 + c] / cntf - mean * mean;
    float v = (x[i] - mean) * rsqrtf(var + EPSB) * g[c] + b[c];
    if (d_cnt[i >> 5] <= 0) v = 0.f;
    out[i] = fmaxf(v, 0.f);
}

// ---------------- MaxPoolingX + FC -------------------------------------------
__global__ void k_poolX(const float* __restrict__ x) {
    int i = blockIdx.x * blockDim.x + threadIdx.x;
    if (i >= MM * 32) return;
    int m = i >> 5, ch = i & 31;
    if (d_cnt[m] <= 0) return;
    int g = m / NCC;
    int gx = min(max((int)floorf(d_pp[m * 3 + 0] / 30.0f), 0), 3);
    int gy = min(max((int)floorf(d_pp[m * 3 + 1] / 25.0f), 0), 3);
    int seg = g * GRD + gy * 4 + gx;
    atomicMaxFloatPos(&d_xg[seg * 32 + ch], x[i]);
}

__global__ void k_fc(const float* __restrict__ fcw, float* __restrict__ out) {
    int b = blockIdx.x;            // BB blocks
    int o = threadIdx.x >> 5;      // 2 warps
    int lane = threadIdx.x & 31;
    float s = 0.f;
    for (int j = lane; j < GRD * 32; j += 32)
        s += d_xg[b * GRD * 32 + j] * fcw[o * GRD * 32 + j];
#pragma unroll
    for (int off = 16; off; off >>= 1) s += __shfl_down_sync(0xffffffff, s, off);
    if (lane == 0) out[b * NOUTC + o] = s;
}

// ---------------- host orchestration -----------------------------------------
extern "C" void kernel_launch(void* const* d_in, const int* in_sizes, int n_in,
                              void* d_out, int out_size) {
    const float* x   = (const float*)d_in[0];
    const float* pos = (const float*)d_in[1];
    const float* ea  = (const float*)d_in[2];
    const float* w[7];
    const float* gm[7];
    const float* bt[7];
    for (int i = 0; i < 7; i++) {
        w[i]  = (const float*)d_in[3 + i];
        gm[i] = (const float*)d_in[10 + i];
        bt[i] = (const float*)d_in[17 + i];
    }
    const float* fcw = (const float*)d_in[24];
    const int* ei    = (const int*)d_in[25];
    const int* batch = (const int*)d_in[26];
    const int* src = ei;
    const int* dst = ei + EE;
    float* out = (float*)d_out;

    void *pdeg, *pcur, *pstats, *pxp, *ppp, *pcnt, *padj, *pmaxv, *pnm, *pxg, *pxu;
    cudaGetSymbolAddress(&pdeg, d_deg);
    cudaGetSymbolAddress(&pcur, d_cur);
    cudaGetSymbolAddress(&pstats, d_stats);
    cudaGetSymbolAddress(&pxp, d_xp);
    cudaGetSymbolAddress(&ppp, d_pp);
    cudaGetSymbolAddress(&pcnt, d_cnt);
    cudaGetSymbolAddress(&padj, d_adj);
    cudaGetSymbolAddress(&pmaxv, d_maxv);
    cudaGetSymbolAddress(&pnm, d_nm);
    cudaGetSymbolAddress(&pxg, d_xg);
    cudaGetSymbolAddress(&pxu, d_xu);
    void* pxB;
    cudaGetSymbolAddress(&pxB, d_xB);

    const int TB = 256;
    const int EG = (EE + TB - 1) / TB;
    const int NG = (NN + TB - 1) / TB;
    const int SB = (NN + 255) / 256;           // 977 scan blocks
    const int AGG_BLKS = 1184;                  // 148 SMs * 8

    // ---- CSR build ----
    cudaMemsetAsync(pdeg, 0, (size_t)NN * 4, 0);
    cudaMemsetAsync(pcur, 0, (size_t)NN * 4, 0);
    k_deg<<<EG, TB>>>(dst);
    k_scanA<<<SB, 256>>>();
    k_scanB<<<1, 1024>>>(SB);
    k_scanC<<<NG, TB>>>();
    k_fill<<<EG, TB>>>(src, dst, ea);

    // ---- conv1: 1 -> 8 ----
    k_nproj<1, 8, false><<<(NN * 8 + TB - 1) / TB, TB>>>(x, w[0]);
    cudaMemsetAsync(pstats, 0, 64 * 4, 0);
    k_aggr<8><<<AGG_BLKS, TB>>>();
    k_mkbn<8><<<1, 8>>>(gm[0], bt[0], (float)NN);

    // ---- conv2: 8 -> 16 ----
    k_nproj<8, 16, true><<<(NN * 16 + TB - 1) / TB, TB>>>((const float*)pxB, w[1]);
    cudaMemsetAsync(pstats, 0, 64 * 4, 0);
    k_aggr<16><<<AGG_BLKS, TB>>>();
    k_mkbn<16><<<1, 16>>>(gm[1], bt[1], (float)NN);

    // ---- conv3: 16 -> 16 ----
    k_nproj<16, 16, true><<<(NN * 16 + TB - 1) / TB, TB>>>((const float*)pxB, w[2]);
    cudaMemsetAsync(pstats, 0, 64 * 4, 0);
    k_aggr<16><<<AGG_BLKS, TB>>>();
    k_mkbn<16><<<1, 16>>>(gm[2], bt[2], (float)NN);

    // ---- conv4: 16 -> 16 ----
    k_nproj<16, 16, true><<<(NN * 16 + TB - 1) / TB, TB>>>((const float*)pxB, w[3]);
    cudaMemsetAsync(pstats, 0, 64 * 4, 0);
    k_aggr<16><<<AGG_BLKS, TB>>>();
    k_mkbn<16><<<1, 16>>>(gm[3], bt[3], (float)NN);

    // ---- conv5: 16 -> 32 ----
    k_nproj<16, 32, true><<<(NN * 32 + TB - 1) / TB, TB>>>((const float*)pxB, w[4]);
    cudaMemsetAsync(pstats, 0, 64 * 4, 0);
    k_aggr<32><<<AGG_BLKS, TB>>>();
    k_mkbn<32><<<1, 32>>>(gm[4], bt[4], (float)NN);

    // ---- MaxPooling (voxel grid), BN5+relu fused in k_cluster ----
    cudaMemsetAsync(pxp, 0, (size_t)MM * 32 * 4, 0);
    cudaMemsetAsync(ppp, 0, (size_t)MM * 3 * 4, 0);
    cudaMemsetAsync(pcnt, 0, (size_t)MM * 4, 0);
    cudaMemsetAsync(padj, 0, (size_t)MM * MM, 0);
    cudaMemsetAsync(pmaxv, 0, 4, 0);
    cudaMemsetAsync(pnm, 0, 4, 0);
    cudaMemsetAsync(pxg, 0, (size_t)BB * GRD * 32 * 4, 0);

    k_cluster<<<NG, TB>>>(pos, batch);
    k_ppfin<<<(MM + TB - 1) / TB, TB>>>();
    k_adj<<<EG, TB>>>(src, dst);
    k_maxv<<<592, TB>>>();

    // ---- conv6: 32 -> 32 (pooled) ----
    k_pz<<<(MM * 256 + TB - 1) / TB, TB>>>((const float*)pxp, w[5]);
    k_pconv<<<MM, 256>>>(d_xt);
    k_pstats<<<1, 1024>>>(d_xt);
    k_pbn<<<(MM * 32 + TB - 1) / TB, TB>>>(d_xt, gm[5], bt[5], (float*)pxu);

    // ---- conv7: 32 -> 32 (pooled) ----
    k_pz<<<(MM * 256 + TB - 1) / TB, TB>>>((const float*)pxu, w[6]);
    k_pconv<<<MM, 256>>>(d_xt);
    k_pstats<<<1, 1024>>>(d_xt);
    k_pbn<<<(MM * 32 + TB - 1) / TB, TB>>>(d_xt, gm[6], bt[6], (float*)pxu);

    // ---- MaxPoolingX + FC ----
    k_poolX<<<(MM * 32 + TB - 1) / TB, TB>>>((const float*)pxu);
    k_fc<<<BB, 64>>>(fcw, out);
}

// round 5
// speedup vs baseline: 1.8120x; 1.8120x over previous
#include <cuda_runtime.h>
#include <math.h>

#define NN   250000
#define EE   1000000
#define BB   25
#define NX_  8
#define NY_  9
#define NCC  72
#define MM   1800
#define GRD  16
#define NOUTC 2
#define EPSB 1e-5f

// ---------------- scratch (device globals; no allocation allowed) -------------
__device__ float d_xA[NN * 32];              // post-BN+relu features
__device__ float d_xB[NN * 32];              // conv outputs (pre-BN, mean-aggregated)
__device__ int   d_deg[NN];
__device__ int   d_off[NN + 1];              // CSR offsets
__device__ int   d_cur[NN];                  // fill cursors
__device__ int   d_part[1024];               // scan partials
__device__ int   d_pbase[1024];
__device__ int   d_esrc[EE];                 // CSR-ordered source node ids
__device__ __align__(16) float d_sbas[(size_t)EE * 8];  // CSR-ordered basis (32MB)
__device__ int   d_clu[NN];
__device__ float d_stats[64];                // [sum(C), sumsq(C)]
__device__ __align__(16) float d_bnsc[32];   // BN scale per channel
__device__ __align__(16) float d_bnsh[32];   // BN shift per channel
__device__ float d_xp[MM * 32];              // pooled features (max pooled)
__device__ float d_pp[MM * 3];               // pooled positions
__device__ int   d_cnt[MM];
__device__ unsigned char d_adj[MM * MM];
__device__ int   d_maxv;                     // float bits (non-negative)
__device__ int   d_nm;                       // number of non-empty cells
__device__ float d_pz[MM * 8 * 32];          // pooled per-node projections
__device__ float d_xt[MM * 32];              // pooled conv raw output
__device__ float d_xu[MM * 32];              // pooled conv post-BN output
__device__ float d_xg[BB * GRD * 32];        // MaxPoolingX output

// ---------------- helpers ----------------------------------------------------
__device__ __forceinline__ void basis8(float p0, float p1, float p2, float* b) {
    p0 = fminf(fmaxf(p0, 0.f), 1.f);
    p1 = fminf(fmaxf(p1, 0.f), 1.f);
    p2 = fminf(fmaxf(p2, 0.f), 1.f);
    float q0 = 1.f - p0, q1 = 1.f - p1, q2 = 1.f - p2;
    b[0] = q0 * q1 * q2; b[1] = p0 * q1 * q2;
    b[2] = q0 * p1 * q2; b[3] = p0 * p1 * q2;
    b[4] = q0 * q1 * p2; b[5] = p0 * q1 * p2;
    b[6] = q0 * p1 * p2; b[7] = p0 * p1 * p2;
}

__device__ __forceinline__ void atomicMaxFloatPos(float* addr, float v) {
    atomicMax(reinterpret_cast<int*>(addr), __float_as_int(v));
}

// ---------------- degree + CSR build -----------------------------------------
__global__ void k_deg(const int* __restrict__ dst) {
    int e = blockIdx.x * blockDim.x + threadIdx.x;
    if (e < EE) atomicAdd(&d_deg[dst[e]], 1);
}

__global__ void k_scanA() {  // 256 threads/block
    __shared__ int sm[256];
    int i = blockIdx.x * 256 + threadIdx.x;
    int v = (i < NN) ? d_deg[i] : 0;
    sm[threadIdx.x] = v;
    __syncthreads();
    for (int off = 1; off < 256; off <<= 1) {
        int t = (threadIdx.x >= off) ? sm[threadIdx.x - off] : 0;
        __syncthreads();
        sm[threadIdx.x] += t;
        __syncthreads();
    }
    if (i < NN) d_off[i] = sm[threadIdx.x] - v;  // exclusive within block
    if (threadIdx.x == 255) d_part[blockIdx.x] = sm[255];
}

__global__ void k_scanB(int nparts) {  // 1 block, 1024 threads
    __shared__ int sm[1024];
    int v = (threadIdx.x < nparts) ? d_part[threadIdx.x] : 0;
    sm[threadIdx.x] = v;
    __syncthreads();
    for (int off = 1; off < 1024; off <<= 1) {
        int t = (threadIdx.x >= off) ? sm[threadIdx.x - off] : 0;
        __syncthreads();
        sm[threadIdx.x] += t;
        __syncthreads();
    }
    if (threadIdx.x < nparts) d_pbase[threadIdx.x] = sm[threadIdx.x] - v;
}

__global__ void k_scanC() {
    int i = blockIdx.x * blockDim.x + threadIdx.x;
    if (i < NN) d_off[i] += d_pbase[i >> 8];
    if (i == 0) d_off[NN] = EE;
}

__global__ void k_fill(const int* __restrict__ src, const int* __restrict__ dst,
                       const float* __restrict__ ea) {
    int e = blockIdx.x * blockDim.x + threadIdx.x;
    if (e >= EE) return;
    int d = dst[e];
    int slot = d_off[d] + atomicAdd(&d_cur[d], 1);
    d_esrc[slot] = src[e];
    float bs[8];
    basis8(ea[3 * e + 0], ea[3 * e + 1], ea[3 * e + 2], bs);
    float4* p = reinterpret_cast<float4*>(d_sbas + (size_t)slot * 8);
    p[0] = make_float4(bs[0], bs[1], bs[2], bs[3]);
    p[1] = make_float4(bs[4], bs[5], bs[6], bs[7]);
}

// ---------------- BN constants ------------------------------------------------
template <int C>
__global__ void k_mkbn(const float* __restrict__ g, const float* __restrict__ b,
                       float cnt) {
    int c = threadIdx.x;  // C threads
    float mean = d_stats[c] / cnt;
    float var = d_stats[C + c] / cnt - mean * mean;
    float s = rsqrtf(var + EPSB) * g[c];
    d_bnsc[c] = s;
    d_bnsh[c] = b[c] - mean * s;
}

// ---------------- BN apply + relu --------------------------------------------
template <int C>
__global__ void k_bnapply() {
    int i = blockIdx.x * blockDim.x + threadIdx.x;
    if (i >= NN * C) return;
    int c = i % C;
    float v = d_xB[i] * d_bnsc[c] + d_bnsh[c];
    d_xA[i] = fmaxf(v, 0.f);
}

// ---------------- fused SplineConv: gather outer-product + node GEMM ----------
// out[d] = ((1/deg) * sum_e b_e (x) x_src(e)) . W_flat[8*CIN, COUT]
// Block: 256 threads = 32 sub-warps of 8 lanes (lane = kernel index s).
// Phase 1: each sub accumulates T[s][0..CIN-1] over its dst's CSR edges.
// Phase 2: shared-memory GEMM (T tile 32 x K) x (W^T), stats fused.
template <int CIN, int COUT>
__global__ __launch_bounds__(256) void k_conv(const float* __restrict__ xin,
                                              const float* __restrict__ W) {
    constexpr int K = 8 * CIN;
    constexpr int KP = K + 4;          // pad (multiple of 4 keeps 16B alignment)
    constexpr int DB = 32;             // dsts per block
    constexpr int DS = 256 / COUT;     // distinct dl per pass
    constexpr int OPT = DB / DS;       // outputs per thread
    __shared__ float Tsh[DB * K];
    __shared__ float Wt[COUT * KP];    // transposed: Wt[c][k]
    __shared__ float ssum[32], ssq[32];
    int tid = threadIdx.x;
    for (int i = tid; i < K * COUT; i += 256) {
        int k = i / COUT, c = i % COUT;
        Wt[c * KP + k] = W[i];
    }
    if (tid < 32) { ssum[tid] = 0.f; ssq[tid] = 0.f; }

    int sub = tid >> 3;
    int s = tid & 7;
    int d = blockIdx.x * DB + sub;
    float T[CIN];
#pragma unroll
    for (int ci = 0; ci < CIN; ci++) T[ci] = 0.f;
    float invdeg = 0.f;
    if (d < NN) {
        int st = d_off[d], en = d_off[d + 1];
        for (int j = st; j < en; j++) {
            float b = d_sbas[(size_t)j * 8 + s];
            int sn = d_esrc[j];
            if (CIN == 1) {
                T[0] += b * xin[sn];
            } else {
                const float4* xp4 = reinterpret_cast<const float4*>(xin + (size_t)sn * CIN);
#pragma unroll
                for (int q = 0; q < CIN / 4; q++) {
                    float4 v = xp4[q];
                    T[4 * q + 0] += b * v.x; T[4 * q + 1] += b * v.y;
                    T[4 * q + 2] += b * v.z; T[4 * q + 3] += b * v.w;
                }
            }
        }
        invdeg = 1.f / fmaxf((float)(en - st), 1.f);   // mean folded into T
    }
#pragma unroll
    for (int ci = 0; ci < CIN; ci++)
        Tsh[sub * K + s * CIN + ci] = T[ci] * invdeg;
    __syncthreads();

    // ---- GEMM phase ----
    int c = tid % COUT;
    int dl = tid / COUT;
    float acc[OPT];
#pragma unroll
    for (int p = 0; p < OPT; p++) acc[p] = 0.f;
#pragma unroll
    for (int k = 0; k < K; k += 4) {
        float4 w4 = *reinterpret_cast<const float4*>(&Wt[c * KP + k]);
#pragma unroll
        for (int p = 0; p < OPT; p++) {
            float4 t4 = *reinterpret_cast<const float4*>(&Tsh[(dl + p * DS) * K + k]);
            acc[p] += w4.x * t4.x + w4.y * t4.y + w4.z * t4.z + w4.w * t4.w;
        }
    }
    float ps = 0.f, pq = 0.f;
#pragma unroll
    for (int p = 0; p < OPT; p++) {
        int dd = blockIdx.x * DB + dl + p * DS;
        if (dd < NN) {
            d_xB[(size_t)dd * COUT + c] = acc[p];
            ps += acc[p]; pq += acc[p] * acc[p];
        }
    }
    atomicAdd(&ssum[c], ps);
    atomicAdd(&ssq[c], pq);
    __syncthreads();
    if (tid < COUT) {
        atomicAdd(&d_stats[tid], ssum[tid]);
        atomicAdd(&d_stats[COUT + tid], ssq[tid]);
    }
}

// ---------------- voxel pooling (BN5+relu fused on read) ----------------------
__global__ void k_cluster(const float* __restrict__ pos, const int* __restrict__ batch) {
    int n = blockIdx.x * blockDim.x + threadIdx.x;
    if (n >= NN) return;
    float p0 = pos[3 * n + 0], p1 = pos[3 * n + 1], p2 = pos[3 * n + 2];
    int cx = min(max((int)floorf(p0 / 16.0f), 0), NX_ - 1);
    int cy = min(max((int)floorf(p1 / 12.0f), 0), NY_ - 1);
    int cl = batch[n] * NCC + cy * NX_ + cx;
    d_clu[n] = cl;
    atomicAdd(&d_cnt[cl], 1);
    atomicAdd(&d_pp[cl * 3 + 0], p0);
    atomicAdd(&d_pp[cl * 3 + 1], p1);
    atomicAdd(&d_pp[cl * 3 + 2], p2);
    const float4* xr = reinterpret_cast<const float4*>(d_xB + (size_t)n * 32);
    const float4* scp = reinterpret_cast<const float4*>(d_bnsc);
    const float4* shp = reinterpret_cast<const float4*>(d_bnsh);
#pragma unroll
    for (int i = 0; i < 8; i++) {
        float4 v = xr[i];
        float4 s4 = scp[i], h4 = shp[i];
        atomicMaxFloatPos(&d_xp[cl * 32 + 4 * i + 0], fmaxf(v.x * s4.x + h4.x, 0.f));
        atomicMaxFloatPos(&d_xp[cl * 32 + 4 * i + 1], fmaxf(v.y * s4.y + h4.y, 0.f));
        atomicMaxFloatPos(&d_xp[cl * 32 + 4 * i + 2], fmaxf(v.z * s4.z + h4.z, 0.f));
        atomicMaxFloatPos(&d_xp[cl * 32 + 4 * i + 3], fmaxf(v.w * s4.w + h4.w, 0.f));
    }
}

__global__ void k_ppfin() {
    int m = blockIdx.x * blockDim.x + threadIdx.x;
    if (m >= MM) return;
    float c = fmaxf((float)d_cnt[m], 1.f);
    d_pp[m * 3 + 0] /= c;
    d_pp[m * 3 + 1] /= c;
    d_pp[m * 3 + 2] /= c;
    if (d_cnt[m] > 0) atomicAdd(&d_nm, 1);
}

__global__ void k_adj(const int* __restrict__ src, const int* __restrict__ dst) {
    int e = blockIdx.x * blockDim.x + threadIdx.x;
    if (e >= EE) return;
    int a = d_clu[src[e]], b = d_clu[dst[e]];
    if (a != b) d_adj[a * MM + b] = 1;
}

__global__ void k_maxv() {
    const int T = gridDim.x * blockDim.x;
    int t = blockIdx.x * blockDim.x + threadIdx.x;
    float mx = 0.f;
    for (int p = t; p < MM * MM; p += T) {
        if (d_adj[p]) {
            int r = p / MM, c = p % MM;
            mx = fmaxf(mx, fabsf(d_pp[c * 3 + 0] - d_pp[r * 3 + 0]));
            mx = fmaxf(mx, fabsf(d_pp[c * 3 + 1] - d_pp[r * 3 + 1]));
            mx = fmaxf(mx, fabsf(d_pp[c * 3 + 2] - d_pp[r * 3 + 2]));
        }
    }
    __shared__ float red[256];
    red[threadIdx.x] = mx;
    __syncthreads();
    for (int o = 128; o > 0; o >>= 1) {
        if (threadIdx.x < o) red[threadIdx.x] = fmaxf(red[threadIdx.x], red[threadIdx.x + o]);
        __syncthreads();
    }
    if (threadIdx.x == 0) atomicMax(&d_maxv, __float_as_int(red[0]));
}

// ---------------- pooled conv: per-node projections z = x . W[s] --------------
__global__ void k_pz(const float* __restrict__ xin, const float* __restrict__ W) {
    int t = blockIdx.x * blockDim.x + threadIdx.x;
    if (t >= MM * 8 * 32) return;
    int co = t & 31;
    int s = (t >> 5) & 7;
    int r = t >> 8;
    float acc = 0.f;
    const float* xr = &xin[r * 32];
    const float* wp = &W[s * 32 * 32 + co];
#pragma unroll
    for (int ci = 0; ci < 32; ci++) acc += xr[ci] * wp[ci * 32];
    d_pz[t] = acc;
}

// ---------------- pooled conv: per-dst aggregation ---------------------------
__global__ void k_pconv(float* __restrict__ out) {
    int c = blockIdx.x;
    int lane = threadIdx.x & 31;
    int w = threadIdx.x >> 5;  // 8 warps
    int g = c / NCC;
    int base = g * NCC;
    float inv = 0.5f / fmaxf(__int_as_float(d_maxv), 1e-9f);
    float pc0 = d_pp[c * 3 + 0], pc1 = d_pp[c * 3 + 1], pc2 = d_pp[c * 3 + 2];
    float acc = 0.f;
    int cnt = 0;
    for (int r = base + w; r < base + NCC; r += 8) {
        if (r == c || !d_adj[r * MM + c]) continue;
        cnt++;
        float bs[8];
        basis8((pc0 - d_pp[r * 3 + 0]) * inv + 0.5f,
               (pc1 - d_pp[r * 3 + 1]) * inv + 0.5f,
               (pc2 - d_pp[r * 3 + 2]) * inv + 0.5f, bs);
        const float* z = &d_pz[r * 256];
#pragma unroll
        for (int s = 0; s < 8; s++) acc += bs[s] * z[s * 32 + lane];
    }
    __shared__ float sa[8][32];
    __shared__ int scn[8];
    sa[w][lane] = acc;
    if (lane == 0) scn[w] = cnt;
    __syncthreads();
    if (w == 0) {
        float a = 0.f;
        int k = 0;
#pragma unroll
        for (int j = 0; j < 8; j++) { a += sa[j][lane]; k += scn[j]; }
        out[c * 32 + lane] = a / fmaxf((float)k, 1.f);
    }
}

// ---------------- pooled (masked) BN stats + finalize ------------------------
__global__ void k_pstats(const float* __restrict__ x) {
    int tid = threadIdx.x;  // one block, 1024 threads
    const int c = tid & 31;
    float sum = 0.f, sq = 0.f;
    for (int i = tid; i < MM * 32; i += 1024) {
        if (d_cnt[i >> 5] > 0) {
            float v = x[i];
            sum += v; sq += v * v;
        }
    }
    __shared__ float ss[32], s2[32];
    if (tid < 32) { ss[tid] = 0.f; s2[tid] = 0.f; }
    __syncthreads();
    atomicAdd(&ss[c], sum);
    atomicAdd(&s2[c], sq);
    __syncthreads();
    if (tid < 32) { d_stats[tid] = ss[tid]; d_stats[32 + tid] = s2[tid]; }
}

__global__ void k_pbn(const float* __restrict__ x, const float* __restrict__ g,
                      const float* __restrict__ b, float* __restrict__ out) {
    int i = blockIdx.x * blockDim.x + threadIdx.x;
    if (i >= MM * 32) return;
    int c = i & 31;
    float cntf = fmaxf((float)d_nm, 1.f);
    float mean = d_stats[c] / cntf;
    float var = d_stats[32 + c] / cntf - mean * mean;
    float v = (x[i] - mean) * rsqrtf(var + EPSB) * g[c] + b[c];
    if (d_cnt[i >> 5] <= 0) v = 0.f;
    out[i] = fmaxf(v, 0.f);
}

// ---------------- MaxPoolingX + FC -------------------------------------------
__global__ void k_poolX(const float* __restrict__ x) {
    int i = blockIdx.x * blockDim.x + threadIdx.x;
    if (i >= MM * 32) return;
    int m = i >> 5, ch = i & 31;
    if (d_cnt[m] <= 0) return;
    int g = m / NCC;
    int gx = min(max((int)floorf(d_pp[m * 3 + 0] / 30.0f), 0), 3);
    int gy = min(max((int)floorf(d_pp[m * 3 + 1] / 25.0f), 0), 3);
    int seg = g * GRD + gy * 4 + gx;
    atomicMaxFloatPos(&d_xg[seg * 32 + ch], x[i]);
}

__global__ void k_fc(const float* __restrict__ fcw, float* __restrict__ out) {
    int b = blockIdx.x;            // BB blocks
    int o = threadIdx.x >> 5;      // 2 warps
    int lane = threadIdx.x & 31;
    float s = 0.f;
    for (int j = lane; j < GRD * 32; j += 32)
        s += d_xg[b * GRD * 32 + j] * fcw[o * GRD * 32 + j];
#pragma unroll
    for (int off = 16; off; off >>= 1) s += __shfl_down_sync(0xffffffff, s, off);
    if (lane == 0) out[b * NOUTC + o] = s;
}

// ---------------- host orchestration -----------------------------------------
extern "C" void kernel_launch(void* const* d_in, const int* in_sizes, int n_in,
                              void* d_out, int out_size) {
    const float* x   = (const float*)d_in[0];
    const float* pos = (const float*)d_in[1];
    const float* ea  = (const float*)d_in[2];
    const float* w[7];
    const float* gm[7];
    const float* bt[7];
    for (int i = 0; i < 7; i++) {
        w[i]  = (const float*)d_in[3 + i];
        gm[i] = (const float*)d_in[10 + i];
        bt[i] = (const float*)d_in[17 + i];
    }
    const float* fcw = (const float*)d_in[24];
    const int* ei    = (const int*)d_in[25];
    const int* batch = (const int*)d_in[26];
    const int* src = ei;
    const int* dst = ei + EE;
    float* out = (float*)d_out;

    void *pdeg, *pcur, *pstats, *pxp, *ppp, *pcnt, *padj, *pmaxv, *pnm, *pxg, *pxu, *pxA;
    cudaGetSymbolAddress(&pdeg, d_deg);
    cudaGetSymbolAddress(&pcur, d_cur);
    cudaGetSymbolAddress(&pstats, d_stats);
    cudaGetSymbolAddress(&pxp, d_xp);
    cudaGetSymbolAddress(&ppp, d_pp);
    cudaGetSymbolAddress(&pcnt, d_cnt);
    cudaGetSymbolAddress(&padj, d_adj);
    cudaGetSymbolAddress(&pmaxv, d_maxv);
    cudaGetSymbolAddress(&pnm, d_nm);
    cudaGetSymbolAddress(&pxg, d_xg);
    cudaGetSymbolAddress(&pxu, d_xu);
    cudaGetSymbolAddress(&pxA, d_xA);

    const int TB = 256;
    const int EG = (EE + TB - 1) / TB;
    const int NG = (NN + TB - 1) / TB;
    const int SB = (NN + 255) / 256;           // scan blocks
    const int DG = (NN + 31) / 32;             // k_conv blocks (32 dsts each)

    // ---- CSR build ----
    cudaMemsetAsync(pdeg, 0, (size_t)NN * 4, 0);
    cudaMemsetAsync(pcur, 0, (size_t)NN * 4, 0);
    k_deg<<<EG, TB>>>(dst);
    k_scanA<<<SB, 256>>>();
    k_scanB<<<1, 1024>>>(SB);
    k_scanC<<<NG, TB>>>();
    k_fill<<<EG, TB>>>(src, dst, ea);

    // ---- conv1: 1 -> 8 ----
    cudaMemsetAsync(pstats, 0, 64 * 4, 0);
    k_conv<1, 8><<<DG, 256>>>(x, w[0]);
    k_mkbn<8><<<1, 8>>>(gm[0], bt[0], (float)NN);
    k_bnapply<8><<<(NN * 8 + TB - 1) / TB, TB>>>();

    // ---- conv2: 8 -> 16 ----
    cudaMemsetAsync(pstats, 0, 64 * 4, 0);
    k_conv<8, 16><<<DG, 256>>>((const float*)pxA, w[1]);
    k_mkbn<16><<<1, 16>>>(gm[1], bt[1], (float)NN);
    k_bnapply<16><<<(NN * 16 + TB - 1) / TB, TB>>>();

    // ---- conv3: 16 -> 16 ----
    cudaMemsetAsync(pstats, 0, 64 * 4, 0);
    k_conv<16, 16><<<DG, 256>>>((const float*)pxA, w[2]);
    k_mkbn<16><<<1, 16>>>(gm[2], bt[2], (float)NN);
    k_bnapply<16><<<(NN * 16 + TB - 1) / TB, TB>>>();

    // ---- conv4: 16 -> 16 ----
    cudaMemsetAsync(pstats, 0, 64 * 4, 0);
    k_conv<16, 16><<<DG, 256>>>((const float*)pxA, w[3]);
    k_mkbn<16><<<1, 16>>>(gm[3], bt[3], (float)NN);
    k_bnapply<16><<<(NN * 16 + TB - 1) / TB, TB>>>();

    // ---- conv5: 16 -> 32 (BN apply fused into k_cluster) ----
    cudaMemsetAsync(pstats, 0, 64 * 4, 0);
    k_conv<16, 32><<<DG, 256>>>((const float*)pxA, w[4]);
    k_mkbn<32><<<1, 32>>>(gm[4], bt[4], (float)NN);

    // ---- MaxPooling (voxel grid) ----
    cudaMemsetAsync(pxp, 0, (size_t)MM * 32 * 4, 0);
    cudaMemsetAsync(ppp, 0, (size_t)MM * 3 * 4, 0);
    cudaMemsetAsync(pcnt, 0, (size_t)MM * 4, 0);
    cudaMemsetAsync(padj, 0, (size_t)MM * MM, 0);
    cudaMemsetAsync(pmaxv, 0, 4, 0);
    cudaMemsetAsync(pnm, 0, 4, 0);
    cudaMemsetAsync(pxg, 0, (size_t)BB * GRD * 32 * 4, 0);

    k_cluster<<<NG, TB>>>(pos, batch);
    k_ppfin<<<(MM + TB - 1) / TB, TB>>>();
    k_adj<<<EG, TB>>>(src, dst);
    k_maxv<<<592, TB>>>();

    // ---- conv6: 32 -> 32 (pooled) ----
    k_pz<<<(MM * 256 + TB - 1) / TB, TB>>>((const float*)pxp, w[5]);
    k_pconv<<<MM, 256>>>(d_xt);
    k_pstats<<<1, 1024>>>(d_xt);
    k_pbn<<<(MM * 32 + TB - 1) / TB, TB>>>(d_xt, gm[5], bt[5], (float*)pxu);

    // ---- conv7: 32 -> 32 (pooled) ----
    k_pz<<<(MM * 256 + TB - 1) / TB, TB>>>((const float*)pxu, w[6]);
    k_pconv<<<MM, 256>>>(d_xt);
    k_pstats<<<1, 1024>>>(d_xt);
    k_pbn<<<(MM * 32 + TB - 1) / TB, TB>>>(d_xt, gm[6], bt[6], (float*)pxu);

    // ---- MaxPoolingX + FC ----
    k_poolX<<<(MM * 32 + TB - 1) / TB, TB>>>((const float*)pxu);
    k_fc<<<BB, 64>>>(fcw, out);
}